// round 11
// baseline (speedup 1.0000x reference)
#include <cuda_runtime.h>
#include <cuda_fp16.h>
#include <stdint.h>
#include <math.h>

#define BB 16
#define NN 1024
#define FF 512

// ---------------- scratch (__device__ globals; no allocs allowed) ----------
__device__ float g_r[BB * NN];
__device__ __half g_adjT[BB * NN * NN];        // [b][i][j] = adj[b][j][i], fp16
__device__ __half g_hst[BB * FF * NN];         // HsT [b][f][j], fp16
__device__ __half g_xb[BB * NN * FF];          // activations [b][node][f], fp16
__device__ __half g_wt[3 * FF * FF];           // W^T per layer [f][k], fp16

// ---------------- base-ISA PTX helpers -------------------------------------
__device__ __forceinline__ uint32_t smem_u32(const void* p) {
    uint32_t a;
    asm("{ .reg .u64 t; cvta.to.shared.u64 t, %1; cvt.u32.u64 %0, t; }"
        : "=r"(a) : "l"(p));
    return a;
}
__device__ __forceinline__ void cp16(uint32_t s, const void* g) {
    asm volatile("cp.async.cg.shared.global [%0], [%1], 16;" :: "r"(s), "l"(g));
}
#define CP_COMMIT() asm volatile("cp.async.commit_group;" ::: "memory")
#define CP_WAIT2() asm volatile("cp.async.wait_group 2;" ::: "memory")

__device__ __forceinline__ void ldsm4(uint32_t* r, uint32_t addr) {
    asm volatile("ldmatrix.sync.aligned.m8n8.x4.shared.b16 {%0,%1,%2,%3}, [%4];"
        : "=r"(r[0]), "=r"(r[1]), "=r"(r[2]), "=r"(r[3]) : "r"(addr));
}
__device__ __forceinline__ void mma_f16(float* c, const uint32_t* a,
                                        const uint32_t* b) {
    asm volatile(
        "mma.sync.aligned.m16n8k16.row.col.f32.f16.f16.f32 "
        "{%0,%1,%2,%3}, {%4,%5,%6,%7}, {%8,%9}, {%0,%1,%2,%3};"
        : "+f"(c[0]), "+f"(c[1]), "+f"(c[2]), "+f"(c[3])
        : "r"(a[0]), "r"(a[1]), "r"(a[2]), "r"(a[3]), "r"(b[0]), "r"(b[1]));
}
__device__ __forceinline__ uint32_t sw128(uint32_t x) { return x ^ ((x >> 3) & 0x70); }

// SMEM: A (16KB, 128 rows) + B (32KB, 256 rows) per stage; 4 stages = 192KB
#define T_A  0
#define T_B  16384
#define STAGE 49152
#define NSTAGE 4
#define SMEM_TOTAL (NSTAGE * STAGE)
#define NTHREADS 512

// ---------------------------------------------------------------------------
__global__ void colsum_kernel(const float* __restrict__ adj, float* __restrict__ r) {
    __shared__ float red[4][64];
    const int jj = threadIdx.x, ii = threadIdx.y;
    const int col = blockIdx.x * 64 + jj;
    const int b = col / NN, j = col % NN;
    const float* a = adj + (size_t)b * NN * NN + j;
    float s = 0.f;
#pragma unroll 8
    for (int i = ii; i < NN; i += 4) s += a[(size_t)i * NN];
    red[ii][jj] = s;
    __syncthreads();
    if (ii == 0) {
        float t = red[0][jj] + red[1][jj] + red[2][jj] + red[3][jj];
        r[col] = (t > 0.f) ? rsqrtf(t) : 0.f;
    }
}

// transpose to single fp16: out[z][C][R] = fp16(in[z][R][C])
__global__ void transpose_half(const float* __restrict__ in,
                               __half* __restrict__ oh, int R, int C) {
    __shared__ float t[32][33];
    const int i0 = blockIdx.x * 32, j0 = blockIdx.y * 32;
    const size_t zb = (size_t)blockIdx.z * R * C;
    const int tx = threadIdx.x, ty = threadIdx.y;
#pragma unroll
    for (int q = 0; q < 4; q++) {
        int j = j0 + ty + q * 8;
        t[ty + q * 8][tx] = in[zb + (size_t)j * C + i0 + tx];
    }
    __syncthreads();
#pragma unroll
    for (int q = 0; q < 4; q++) {
        int i = i0 + ty + q * 8;
        oh[zb + (size_t)i * R + j0 + tx] = __float2half(t[tx][ty + q * 8]);
    }
}

// transpose all three W matrices in one launch (z selects layer)
__global__ void transpose_w3(const float* __restrict__ W1,
                             const float* __restrict__ W2,
                             const float* __restrict__ W3,
                             __half* __restrict__ oh) {
    __shared__ float t[32][33];
    const int i0 = blockIdx.x * 32, j0 = blockIdx.y * 32;
    const int z = blockIdx.z;
    const float* in = (z == 0) ? W1 : (z == 1) ? W2 : W3;
    __half* outp = oh + (size_t)z * FF * FF;
    const int tx = threadIdx.x, ty = threadIdx.y;
#pragma unroll
    for (int q = 0; q < 4; q++) {
        int j = j0 + ty + q * 8;
        t[ty + q * 8][tx] = in[(size_t)j * FF + i0 + tx];
    }
    __syncthreads();
#pragma unroll
    for (int q = 0; q < 4; q++) {
        int i = i0 + ty + q * 8;
        outp[(size_t)i * FF + j0 + tx] = __float2half(t[tx][ty + q * 8]);
    }
}

// elementwise fp32 -> fp16 convert (float4 vectorized)
__global__ void convert_half(const float* __restrict__ in,
                             __half* __restrict__ oh, int n4) {
    int i = blockIdx.x * 256 + threadIdx.x;
    if (i >= n4) return;
    float4 v = ((const float4*)in)[i];
    ((__half2*)oh)[i * 2 + 0] = __halves2half2(__float2half(v.x), __float2half(v.y));
    ((__half2*)oh)[i * 2 + 1] = __halves2half2(__float2half(v.z), __float2half(v.w));
}

// ---------------------------------------------------------------------------
// HMMA GEMM: D[128m x 256n] = sum_k A[m,k]*B[n,k]   (fp16 in, fp32 acc)
//   512 threads, 16 warps, warp tile 64x32 (2x8 warp grid), K-chunk 64,
//   4-stage cp.async pipeline, register-double-buffered fragments.
//   mode 0: out = r[n]*D                -> HsT fp16 (m=f, n=j)
//   mode 1: out = relu(r[m]*D+bias[n])  -> Xb fp16  (m=i, n=f)
//   mode 2: out = r[m]*D+bias[n]        -> fp32     (m=i, n=f)
// ---------------------------------------------------------------------------
__global__ void __launch_bounds__(NTHREADS, 1)
gcn_gemm(const __half* __restrict__ Aop, const __half* __restrict__ Bop,
         const float* __restrict__ r, const float* __restrict__ bias,
         int lda, size_t aBatch, int ldb, size_t bBatch, int nk, int mode,
         float* __restrict__ outF, __half* __restrict__ oH) {
    extern __shared__ char smem[];
    const uint32_t smb = smem_u32(smem);
    const int tid = threadIdx.x, lane = tid & 31, wid = tid >> 5;
    const int b = blockIdx.z;
    const int m0 = blockIdx.y * 128;
    const int n0 = blockIdx.x * 256;
    const int wr = wid & 1, wc = wid >> 1;      // 2x8 warp grid
    const int m0w = wr * 64, n0w = wc * 32;

    const __half* aP = Aop + b * aBatch + (size_t)m0 * lda;
    const __half* bP = Bop + b * bBatch + (size_t)n0 * ldb;

    auto load_stage = [&](int kc, int buf) {
        const uint32_t sb = smb + buf * STAGE;
#pragma unroll
        for (int i = 0; i < 2; i++) {           // A: 1024 chunk16s
            const int chunk = i * NTHREADS + tid;
            const int row = chunk >> 3, c16 = chunk & 7;
            const uint32_t so = sw128((uint32_t)row * 128 + c16 * 16);
            cp16(sb + T_A + so, aP + (size_t)row * lda + kc * 64 + c16 * 8);
        }
#pragma unroll
        for (int i = 0; i < 4; i++) {           // B: 2048 chunk16s
            const int chunk = i * NTHREADS + tid;
            const int row = chunk >> 3, c16 = chunk & 7;
            const uint32_t so = sw128((uint32_t)row * 128 + c16 * 16);
            cp16(sb + T_B + so, bP + (size_t)row * ldb + kc * 64 + c16 * 8);
        }
    };

    const uint32_t rowA = (uint32_t)(m0w + (lane & 15)) * 128 + (lane >> 4) * 16;
    const uint32_t rowB = (uint32_t)(n0w + ((lane >> 4) << 3) + (lane & 7)) * 128 +
                          ((lane >> 3) & 1) * 16;

    float acc[4][4][4];
#pragma unroll
    for (int a = 0; a < 4; a++)
#pragma unroll
        for (int c = 0; c < 4; c++)
#pragma unroll
            for (int d = 0; d < 4; d++) acc[a][c][d] = 0.f;

    // 4-stage pipeline prologue (always-commit keeps wait_group invariant)
    load_stage(0, 0);
    CP_COMMIT();
    if (nk > 1) load_stage(1, 1);
    CP_COMMIT();
    if (nk > 2) load_stage(2, 2);
    CP_COMMIT();

    int buf = 0;
    for (int s = 0; s < nk; s++) {
        CP_WAIT2();              // stage s complete (<=2 newest groups pending)
        __syncthreads();
        if (s + 3 < nk) load_stage(s + 3, (buf + 3) & 3);
        CP_COMMIT();             // may be empty; keeps group-count invariant

        const uint32_t sb = smb + buf * STAGE;
        uint32_t Af[2][4][4], Bf[2][2][4];
        // preload kt=0 fragments
#pragma unroll
        for (int mi = 0; mi < 4; mi++)
            ldsm4(Af[0][mi], sb + T_A + sw128(rowA + mi * 2048));
#pragma unroll
        for (int n2 = 0; n2 < 2; n2++)
            ldsm4(Bf[0][n2], sb + T_B + sw128(rowB + n2 * 2048));
#pragma unroll
        for (int kt = 0; kt < 4; kt++) {
            const int cur = kt & 1, nxt = cur ^ 1;
            if (kt < 3) {        // prefetch kt+1 fragments during kt's MMAs
#pragma unroll
                for (int mi = 0; mi < 4; mi++)
                    ldsm4(Af[nxt][mi],
                          sb + T_A + sw128(rowA + mi * 2048 + (kt + 1) * 32));
#pragma unroll
                for (int n2 = 0; n2 < 2; n2++)
                    ldsm4(Bf[nxt][n2],
                          sb + T_B + sw128(rowB + n2 * 2048 + (kt + 1) * 32));
            }
#pragma unroll
            for (int mi = 0; mi < 4; mi++)
#pragma unroll
                for (int ni = 0; ni < 4; ni++)
                    mma_f16(acc[mi][ni], Af[cur][mi],
                            &Bf[cur][ni >> 1][(ni & 1) * 2]);
        }
        buf = (buf + 1) & 3;
    }

    // ---------------- epilogue --------------------------------------------
    const int g = lane >> 2, cp2 = (lane & 3) * 2;
    const float* rr = r + b * NN;

    if (mode == 0) {
#pragma unroll
        for (int mi = 0; mi < 4; mi++)
#pragma unroll
            for (int h = 0; h < 2; h++) {
                const int f = m0 + m0w + mi * 16 + g + h * 8;
                const size_t rowb = ((size_t)b * FF + f) * NN;
#pragma unroll
                for (int ni = 0; ni < 4; ni++) {
                    const int j = n0 + n0w + ni * 8 + cp2;
                    float v0 = acc[mi][ni][h * 2 + 0] * rr[j];
                    float v1 = acc[mi][ni][h * 2 + 1] * rr[j + 1];
                    *(__half2*)(oH + rowb + j) =
                        __halves2half2(__float2half(v0), __float2half(v1));
                }
            }
    } else if (mode == 1) {
#pragma unroll
        for (int mi = 0; mi < 4; mi++)
#pragma unroll
            for (int h = 0; h < 2; h++) {
                const int i = m0 + m0w + mi * 16 + g + h * 8;
                const float sc = rr[i];
                const size_t rowb = ((size_t)b * NN + i) * FF;
#pragma unroll
                for (int ni = 0; ni < 4; ni++) {
                    const int f = n0 + n0w + ni * 8 + cp2;
                    float v0 = fmaxf(sc * acc[mi][ni][h * 2 + 0] + bias[f], 0.f);
                    float v1 = fmaxf(sc * acc[mi][ni][h * 2 + 1] + bias[f + 1], 0.f);
                    *(__half2*)(oH + rowb + f) =
                        __halves2half2(__float2half(v0), __float2half(v1));
                }
            }
    } else {
#pragma unroll
        for (int mi = 0; mi < 4; mi++)
#pragma unroll
            for (int h = 0; h < 2; h++) {
                const int i = m0 + m0w + mi * 16 + g + h * 8;
                const float sc = rr[i];
                const size_t rowb = ((size_t)b * NN + i) * FF;
#pragma unroll
                for (int ni = 0; ni < 4; ni++) {
                    const int f = n0 + n0w + ni * 8 + cp2;
                    float2 v;
                    v.x = sc * acc[mi][ni][h * 2 + 0] + bias[f];
                    v.y = sc * acc[mi][ni][h * 2 + 1] + bias[f + 1];
                    *(float2*)(outF + rowb + f) = v;
                }
            }
    }
}

// ---------------------------------------------------------------------------
extern "C" void kernel_launch(void* const* d_in, const int* in_sizes, int n_in,
                              void* d_out, int out_size) {
    const float* X0  = (const float*)d_in[0];
    const float* adj = (const float*)d_in[1];
    const float* W1  = (const float*)d_in[2];
    const float* b1  = (const float*)d_in[3];
    const float* W2  = (const float*)d_in[4];
    const float* b2  = (const float*)d_in[5];
    const float* W3  = (const float*)d_in[6];
    const float* b3  = (const float*)d_in[7];
    float* out = (float*)d_out;

    float* r;
    __half *atp, *hst, *xb, *wt;
    cudaGetSymbolAddress((void**)&r,   g_r);
    cudaGetSymbolAddress((void**)&atp, g_adjT);
    cudaGetSymbolAddress((void**)&hst, g_hst);
    cudaGetSymbolAddress((void**)&xb,  g_xb);
    cudaGetSymbolAddress((void**)&wt,  g_wt);

    cudaFuncSetAttribute(gcn_gemm, cudaFuncAttributeMaxDynamicSharedMemorySize,
                         SMEM_TOTAL);

    // prep
    colsum_kernel<<<BB * NN / 64, dim3(64, 4)>>>(adj, r);                 // 0
    transpose_half<<<dim3(32, 32, BB), dim3(32, 8)>>>(adj, atp, NN, NN);  // 1
    transpose_w3<<<dim3(16, 16, 3), dim3(32, 8)>>>(W1, W2, W3, wt);       // 2
    convert_half<<<BB * NN * FF / 4 / 256, 256>>>(X0, xb, BB * NN * FF / 4); // 3

    const dim3 g1(NN / 256, FF / 128, BB);   // GEMM1: HsT[f,j]  (4,4,16)
    const dim3 g2(FF / 256, NN / 128, BB);   // GEMM2: Y[i,f]    (2,8,16)
    const float* biases[3] = {b1, b2, b3};

    for (int l = 0; l < 3; l++) {
        // GEMM1: A = W^T [f][k] (lda=FF), B = Xb [j][k] (ldb=FF)
        gcn_gemm<<<g1, NTHREADS, SMEM_TOTAL>>>(
            wt + l * FF * FF, xb, r, (const float*)0,
            FF, (size_t)0, FF, (size_t)NN * FF, FF / 64, 0,
            (float*)0, hst);
        // GEMM2: A = adjT [i][j] (lda=NN), B = HsT [f][j] (ldb=NN)
        const int mode = (l == 2) ? 2 : 1;
        gcn_gemm<<<g2, NTHREADS, SMEM_TOTAL>>>(
            atp, hst, r, biases[l],
            NN, (size_t)NN * NN, NN, (size_t)FF * NN, NN / 64, mode,
            out, xb);
    }
}

// round 12
// speedup vs baseline: 1.4843x; 1.4843x over previous
#include <cuda_runtime.h>
#include <cuda_fp16.h>
#include <stdint.h>
#include <math.h>

#define BB 16
#define NN 1024
#define FF 512

// ---------------- scratch (__device__ globals; no allocs allowed) ----------
__device__ float g_r[BB * NN];
__device__ __half g_adjT[BB * NN * NN];        // [b][i][j] = adj[b][j][i], fp16
__device__ __half g_hst[BB * FF * NN];         // HsT [b][f][j], fp16
__device__ __half g_xb[BB * NN * FF];          // activations [b][node][f], fp16
__device__ __half g_wt[3 * FF * FF];           // W^T per layer [f][k], fp16

// ---------------- base-ISA PTX helpers -------------------------------------
__device__ __forceinline__ uint32_t smem_u32(const void* p) {
    uint32_t a;
    asm("{ .reg .u64 t; cvta.to.shared.u64 t, %1; cvt.u32.u64 %0, t; }"
        : "=r"(a) : "l"(p));
    return a;
}
__device__ __forceinline__ void cp16(uint32_t s, const void* g) {
    asm volatile("cp.async.cg.shared.global [%0], [%1], 16;" :: "r"(s), "l"(g));
}
#define CP_COMMIT() asm volatile("cp.async.commit_group;" ::: "memory")
#define CP_WAIT1() asm volatile("cp.async.wait_group 1;" ::: "memory")

__device__ __forceinline__ void ldsm4(uint32_t* r, uint32_t addr) {
    asm volatile("ldmatrix.sync.aligned.m8n8.x4.shared.b16 {%0,%1,%2,%3}, [%4];"
        : "=r"(r[0]), "=r"(r[1]), "=r"(r[2]), "=r"(r[3]) : "r"(addr));
}
__device__ __forceinline__ void mma_f16(float* c, const uint32_t* a,
                                        const uint32_t* b) {
    asm volatile(
        "mma.sync.aligned.m16n8k16.row.col.f32.f16.f16.f32 "
        "{%0,%1,%2,%3}, {%4,%5,%6,%7}, {%8,%9}, {%0,%1,%2,%3};"
        : "+f"(c[0]), "+f"(c[1]), "+f"(c[2]), "+f"(c[3])
        : "r"(a[0]), "r"(a[1]), "r"(a[2]), "r"(a[3]), "r"(b[0]), "r"(b[1]));
}
__device__ __forceinline__ uint32_t sw128(uint32_t x) { return x ^ ((x >> 3) & 0x70); }

// SMEM: A (16KB, 128 rows) + B (32KB, 256 rows) per stage; 3 stages = 144KB
#define T_A  0
#define T_B  16384
#define STAGE 49152
#define NSTAGE 3
#define SMEM_TOTAL (NSTAGE * STAGE)

// ---------------------------------------------------------------------------
__global__ void colsum_kernel(const float* __restrict__ adj, float* __restrict__ r) {
    __shared__ float red[4][64];
    const int jj = threadIdx.x, ii = threadIdx.y;
    const int col = blockIdx.x * 64 + jj;
    const int b = col / NN, j = col % NN;
    const float* a = adj + (size_t)b * NN * NN + j;
    float s = 0.f;
#pragma unroll 8
    for (int i = ii; i < NN; i += 4) s += a[(size_t)i * NN];
    red[ii][jj] = s;
    __syncthreads();
    if (ii == 0) {
        float t = red[0][jj] + red[1][jj] + red[2][jj] + red[3][jj];
        r[col] = (t > 0.f) ? rsqrtf(t) : 0.f;
    }
}

// transpose to single fp16: out[z][C][R] = fp16(in[z][R][C])
__global__ void transpose_half(const float* __restrict__ in,
                               __half* __restrict__ oh, int R, int C) {
    __shared__ float t[32][33];
    const int i0 = blockIdx.x * 32, j0 = blockIdx.y * 32;
    const size_t zb = (size_t)blockIdx.z * R * C;
    const int tx = threadIdx.x, ty = threadIdx.y;
#pragma unroll
    for (int q = 0; q < 4; q++) {
        int j = j0 + ty + q * 8;
        t[ty + q * 8][tx] = in[zb + (size_t)j * C + i0 + tx];
    }
    __syncthreads();
#pragma unroll
    for (int q = 0; q < 4; q++) {
        int i = i0 + ty + q * 8;
        oh[zb + (size_t)i * R + j0 + tx] = __float2half(t[tx][ty + q * 8]);
    }
}

// transpose all three W matrices in one launch (z selects layer)
__global__ void transpose_w3(const float* __restrict__ W1,
                             const float* __restrict__ W2,
                             const float* __restrict__ W3,
                             __half* __restrict__ oh) {
    __shared__ float t[32][33];
    const int i0 = blockIdx.x * 32, j0 = blockIdx.y * 32;
    const int z = blockIdx.z;
    const float* in = (z == 0) ? W1 : (z == 1) ? W2 : W3;
    __half* outp = oh + (size_t)z * FF * FF;
    const int tx = threadIdx.x, ty = threadIdx.y;
#pragma unroll
    for (int q = 0; q < 4; q++) {
        int j = j0 + ty + q * 8;
        t[ty + q * 8][tx] = in[(size_t)j * FF + i0 + tx];
    }
    __syncthreads();
#pragma unroll
    for (int q = 0; q < 4; q++) {
        int i = i0 + ty + q * 8;
        outp[(size_t)i * FF + j0 + tx] = __float2half(t[tx][ty + q * 8]);
    }
}

// elementwise fp32 -> fp16 convert (float4 vectorized)
__global__ void convert_half(const float* __restrict__ in,
                             __half* __restrict__ oh, int n4) {
    int i = blockIdx.x * 256 + threadIdx.x;
    if (i >= n4) return;
    float4 v = ((const float4*)in)[i];
    ((__half2*)oh)[i * 2 + 0] = __halves2half2(__float2half(v.x), __float2half(v.y));
    ((__half2*)oh)[i * 2 + 1] = __halves2half2(__float2half(v.z), __float2half(v.w));
}

// ---------------------------------------------------------------------------
// HMMA GEMM: D[128m x 256n] = sum_k A[m,k]*B[n,k]   (fp16 in, fp32 acc)
//   256 threads, 8 warps, warp tile 64x64 (2x4 warp grid), K-chunk 64,
//   3-stage cp.async pipeline, register-double-buffered fragments.
//   mode 0: out = r[n]*D                -> HsT fp16 (m=f, n=j)
//   mode 1: out = relu(r[m]*D+bias[n])  -> Xb fp16  (m=i, n=f)
//   mode 2: out = r[m]*D+bias[n]        -> fp32     (m=i, n=f)
// ---------------------------------------------------------------------------
__global__ void __launch_bounds__(256, 1)
gcn_gemm(const __half* __restrict__ Aop, const __half* __restrict__ Bop,
         const float* __restrict__ r, const float* __restrict__ bias,
         int lda, size_t aBatch, int ldb, size_t bBatch, int nk, int mode,
         float* __restrict__ outF, __half* __restrict__ oH) {
    extern __shared__ char smem[];
    const uint32_t smb = smem_u32(smem);
    const int tid = threadIdx.x, lane = tid & 31, wid = tid >> 5;
    const int b = blockIdx.z;
    const int m0 = blockIdx.y * 128;
    const int n0 = blockIdx.x * 256;
    const int wr = wid & 1, wc = wid >> 1;      // 2x4 warp grid
    const int m0w = wr * 64, n0w = wc * 64;

    const __half* aP = Aop + b * aBatch + (size_t)m0 * lda;
    const __half* bP = Bop + b * bBatch + (size_t)n0 * ldb;

    auto load_stage = [&](int kc, int buf) {
        const uint32_t sb = smb + buf * STAGE;
#pragma unroll
        for (int i = 0; i < 4; i++) {           // A: 1024 chunk16s
            const int chunk = i * 256 + tid;
            const int row = chunk >> 3, c16 = chunk & 7;
            const uint32_t so = sw128((uint32_t)row * 128 + c16 * 16);
            cp16(sb + T_A + so, aP + (size_t)row * lda + kc * 64 + c16 * 8);
        }
#pragma unroll
        for (int i = 0; i < 8; i++) {           // B: 2048 chunk16s
            const int chunk = i * 256 + tid;
            const int row = chunk >> 3, c16 = chunk & 7;
            const uint32_t so = sw128((uint32_t)row * 128 + c16 * 16);
            cp16(sb + T_B + so, bP + (size_t)row * ldb + kc * 64 + c16 * 8);
        }
    };

    const uint32_t rowA = (uint32_t)(m0w + (lane & 15)) * 128 + (lane >> 4) * 16;
    const uint32_t rowB = (uint32_t)(n0w + ((lane >> 4) << 3) + (lane & 7)) * 128 +
                          ((lane >> 3) & 1) * 16;

    float acc[4][8][4];
#pragma unroll
    for (int a = 0; a < 4; a++)
#pragma unroll
        for (int c = 0; c < 8; c++)
#pragma unroll
            for (int d = 0; d < 4; d++) acc[a][c][d] = 0.f;

    load_stage(0, 0);
    CP_COMMIT();
    if (nk > 1) load_stage(1, 1);
    CP_COMMIT();

    int buf = 0;
    for (int s = 0; s < nk; s++) {
        CP_WAIT1();
        __syncthreads();
        if (s + 2 < nk) load_stage(s + 2, (buf + 2) % NSTAGE);
        CP_COMMIT();

        const uint32_t sb = smb + buf * STAGE;
        uint32_t Af[2][4][4], Bf[2][4][4];
        // preload kt=0 fragments
#pragma unroll
        for (int mi = 0; mi < 4; mi++)
            ldsm4(Af[0][mi], sb + T_A + sw128(rowA + mi * 2048));
#pragma unroll
        for (int n2 = 0; n2 < 4; n2++)
            ldsm4(Bf[0][n2], sb + T_B + sw128(rowB + n2 * 2048));
#pragma unroll
        for (int kt = 0; kt < 4; kt++) {
            const int cur = kt & 1, nxt = cur ^ 1;
            if (kt < 3) {        // prefetch kt+1 fragments during kt's MMAs
#pragma unroll
                for (int mi = 0; mi < 4; mi++)
                    ldsm4(Af[nxt][mi],
                          sb + T_A + sw128(rowA + mi * 2048 + (kt + 1) * 32));
#pragma unroll
                for (int n2 = 0; n2 < 4; n2++)
                    ldsm4(Bf[nxt][n2],
                          sb + T_B + sw128(rowB + n2 * 2048 + (kt + 1) * 32));
            }
#pragma unroll
            for (int mi = 0; mi < 4; mi++)
#pragma unroll
                for (int ni = 0; ni < 8; ni++)
                    mma_f16(acc[mi][ni], Af[cur][mi],
                            &Bf[cur][ni >> 1][(ni & 1) * 2]);
        }
        buf = (buf + 1) % NSTAGE;
    }

    // ---------------- epilogue --------------------------------------------
    const int g = lane >> 2, cp2 = (lane & 3) * 2;
    const float* rr = r + b * NN;

    if (mode == 0) {
#pragma unroll
        for (int mi = 0; mi < 4; mi++)
#pragma unroll
            for (int h = 0; h < 2; h++) {
                const int f = m0 + m0w + mi * 16 + g + h * 8;
                const size_t rowb = ((size_t)b * FF + f) * NN;
#pragma unroll
                for (int ni = 0; ni < 8; ni++) {
                    const int j = n0 + n0w + ni * 8 + cp2;
                    float v0 = acc[mi][ni][h * 2 + 0] * rr[j];
                    float v1 = acc[mi][ni][h * 2 + 1] * rr[j + 1];
                    *(__half2*)(oH + rowb + j) =
                        __halves2half2(__float2half(v0), __float2half(v1));
                }
            }
    } else if (mode == 1) {
#pragma unroll
        for (int mi = 0; mi < 4; mi++)
#pragma unroll
            for (int h = 0; h < 2; h++) {
                const int i = m0 + m0w + mi * 16 + g + h * 8;
                const float sc = rr[i];
                const size_t rowb = ((size_t)b * NN + i) * FF;
#pragma unroll
                for (int ni = 0; ni < 8; ni++) {
                    const int f = n0 + n0w + ni * 8 + cp2;
                    float v0 = fmaxf(sc * acc[mi][ni][h * 2 + 0] + bias[f], 0.f);
                    float v1 = fmaxf(sc * acc[mi][ni][h * 2 + 1] + bias[f + 1], 0.f);
                    *(__half2*)(oH + rowb + f) =
                        __halves2half2(__float2half(v0), __float2half(v1));
                }
            }
    } else {
#pragma unroll
        for (int mi = 0; mi < 4; mi++)
#pragma unroll
            for (int h = 0; h < 2; h++) {
                const int i = m0 + m0w + mi * 16 + g + h * 8;
                const float sc = rr[i];
                const size_t rowb = ((size_t)b * NN + i) * FF;
#pragma unroll
                for (int ni = 0; ni < 8; ni++) {
                    const int f = n0 + n0w + ni * 8 + cp2;
                    float2 v;
                    v.x = sc * acc[mi][ni][h * 2 + 0] + bias[f];
                    v.y = sc * acc[mi][ni][h * 2 + 1] + bias[f + 1];
                    *(float2*)(outF + rowb + f) = v;
                }
            }
    }
}

// ---------------------------------------------------------------------------
extern "C" void kernel_launch(void* const* d_in, const int* in_sizes, int n_in,
                              void* d_out, int out_size) {
    const float* X0  = (const float*)d_in[0];
    const float* adj = (const float*)d_in[1];
    const float* W1  = (const float*)d_in[2];
    const float* b1  = (const float*)d_in[3];
    const float* W2  = (const float*)d_in[4];
    const float* b2  = (const float*)d_in[5];
    const float* W3  = (const float*)d_in[6];
    const float* b3  = (const float*)d_in[7];
    float* out = (float*)d_out;

    float* r;
    __half *atp, *hst, *xb, *wt;
    cudaGetSymbolAddress((void**)&r,   g_r);
    cudaGetSymbolAddress((void**)&atp, g_adjT);
    cudaGetSymbolAddress((void**)&hst, g_hst);
    cudaGetSymbolAddress((void**)&xb,  g_xb);
    cudaGetSymbolAddress((void**)&wt,  g_wt);

    cudaFuncSetAttribute(gcn_gemm, cudaFuncAttributeMaxDynamicSharedMemorySize,
                         SMEM_TOTAL);

    // prep
    colsum_kernel<<<BB * NN / 64, dim3(64, 4)>>>(adj, r);                 // 0
    transpose_half<<<dim3(32, 32, BB), dim3(32, 8)>>>(adj, atp, NN, NN);  // 1
    transpose_w3<<<dim3(16, 16, 3), dim3(32, 8)>>>(W1, W2, W3, wt);       // 2
    convert_half<<<BB * NN * FF / 4 / 256, 256>>>(X0, xb, BB * NN * FF / 4); // 3

    const dim3 g1(NN / 256, FF / 128, BB);   // GEMM1: HsT[f,j]  (4,4,16)
    const dim3 g2(FF / 256, NN / 128, BB);   // GEMM2: Y[i,f]    (2,8,16)
    const float* biases[3] = {b1, b2, b3};

    for (int l = 0; l < 3; l++) {
        // GEMM1: A = W^T [f][k] (lda=FF), B = Xb [j][k] (ldb=FF)
        gcn_gemm<<<g1, 256, SMEM_TOTAL>>>(
            wt + l * FF * FF, xb, r, (const float*)0,
            FF, (size_t)0, FF, (size_t)NN * FF, FF / 64, 0,
            (float*)0, hst);
        // GEMM2: A = adjT [i][j] (lda=NN), B = HsT [f][j] (ldb=NN)
        const int mode = (l == 2) ? 2 : 1;
        gcn_gemm<<<g2, 256, SMEM_TOTAL>>>(
            atp, hst, r, biases[l],
            NN, (size_t)NN * NN, NN, (size_t)FF * NN, NN / 64, mode,
            out, xb);
    }
}

// round 13
// speedup vs baseline: 1.5564x; 1.0485x over previous
#include <cuda_runtime.h>
#include <cuda_fp16.h>
#include <stdint.h>
#include <math.h>

#define BB 16
#define NN 1024
#define FF 512

// ---------------- scratch (__device__ globals; no allocs allowed) ----------
__device__ float g_r[BB * NN];
__device__ __half g_adjT[BB * NN * NN];        // [b][i][j] = adj[b][j][i], fp16
__device__ __half g_hst[BB * FF * NN];         // HsT [b][f][j], fp16
__device__ __half g_xb[BB * NN * FF];          // activations [b][node][f], fp16
__device__ __half g_wt[3 * FF * FF];           // W^T per layer [f][k], fp16

// ---------------- base-ISA PTX helpers -------------------------------------
__device__ __forceinline__ uint32_t smem_u32(const void* p) {
    uint32_t a;
    asm("{ .reg .u64 t; cvta.to.shared.u64 t, %1; cvt.u32.u64 %0, t; }"
        : "=r"(a) : "l"(p));
    return a;
}
__device__ __forceinline__ void cp16(uint32_t s, const void* g) {
    asm volatile("cp.async.cg.shared.global [%0], [%1], 16;" :: "r"(s), "l"(g));
}
#define CP_COMMIT() asm volatile("cp.async.commit_group;" ::: "memory")
#define CP_WAIT1() asm volatile("cp.async.wait_group 1;" ::: "memory")

__device__ __forceinline__ void ldsm4(uint32_t* r, uint32_t addr) {
    asm volatile("ldmatrix.sync.aligned.m8n8.x4.shared.b16 {%0,%1,%2,%3}, [%4];"
        : "=r"(r[0]), "=r"(r[1]), "=r"(r[2]), "=r"(r[3]) : "r"(addr));
}
__device__ __forceinline__ void mma_f16(float* c, const uint32_t* a,
                                        const uint32_t* b) {
    asm volatile(
        "mma.sync.aligned.m16n8k16.row.col.f32.f16.f16.f32 "
        "{%0,%1,%2,%3}, {%4,%5,%6,%7}, {%8,%9}, {%0,%1,%2,%3};"
        : "+f"(c[0]), "+f"(c[1]), "+f"(c[2]), "+f"(c[3])
        : "r"(a[0]), "r"(a[1]), "r"(a[2]), "r"(a[3]), "r"(b[0]), "r"(b[1]));
}
__device__ __forceinline__ uint32_t sw128(uint32_t x) { return x ^ ((x >> 3) & 0x70); }

// SMEM: A (16KB, 128 rows) + B (16KB, 128 rows) per stage; 3 stages = 96KB/CTA
#define T_A  0
#define T_B  16384
#define STAGE 32768
#define NSTAGE 3
#define SMEM_TOTAL (NSTAGE * STAGE)
#define NTHREADS 128

// ---------------------------------------------------------------------------
__global__ void colsum_kernel(const float* __restrict__ adj, float* __restrict__ r) {
    __shared__ float red[4][64];
    const int jj = threadIdx.x, ii = threadIdx.y;
    const int col = blockIdx.x * 64 + jj;
    const int b = col / NN, j = col % NN;
    const float* a = adj + (size_t)b * NN * NN + j;
    float s = 0.f;
#pragma unroll 8
    for (int i = ii; i < NN; i += 4) s += a[(size_t)i * NN];
    red[ii][jj] = s;
    __syncthreads();
    if (ii == 0) {
        float t = red[0][jj] + red[1][jj] + red[2][jj] + red[3][jj];
        r[col] = (t > 0.f) ? rsqrtf(t) : 0.f;
    }
}

// transpose to single fp16: out[z][C][R] = fp16(in[z][R][C])
__global__ void transpose_half(const float* __restrict__ in,
                               __half* __restrict__ oh, int R, int C) {
    __shared__ float t[32][33];
    const int i0 = blockIdx.x * 32, j0 = blockIdx.y * 32;
    const size_t zb = (size_t)blockIdx.z * R * C;
    const int tx = threadIdx.x, ty = threadIdx.y;
#pragma unroll
    for (int q = 0; q < 4; q++) {
        int j = j0 + ty + q * 8;
        t[ty + q * 8][tx] = in[zb + (size_t)j * C + i0 + tx];
    }
    __syncthreads();
#pragma unroll
    for (int q = 0; q < 4; q++) {
        int i = i0 + ty + q * 8;
        oh[zb + (size_t)i * R + j0 + tx] = __float2half(t[tx][ty + q * 8]);
    }
}

// transpose all three W matrices in one launch (z selects layer)
__global__ void transpose_w3(const float* __restrict__ W1,
                             const float* __restrict__ W2,
                             const float* __restrict__ W3,
                             __half* __restrict__ oh) {
    __shared__ float t[32][33];
    const int i0 = blockIdx.x * 32, j0 = blockIdx.y * 32;
    const int z = blockIdx.z;
    const float* in = (z == 0) ? W1 : (z == 1) ? W2 : W3;
    __half* outp = oh + (size_t)z * FF * FF;
    const int tx = threadIdx.x, ty = threadIdx.y;
#pragma unroll
    for (int q = 0; q < 4; q++) {
        int j = j0 + ty + q * 8;
        t[ty + q * 8][tx] = in[(size_t)j * FF + i0 + tx];
    }
    __syncthreads();
#pragma unroll
    for (int q = 0; q < 4; q++) {
        int i = i0 + ty + q * 8;
        outp[(size_t)i * FF + j0 + tx] = __float2half(t[tx][ty + q * 8]);
    }
}

// elementwise fp32 -> fp16 convert (float4 vectorized)
__global__ void convert_half(const float* __restrict__ in,
                             __half* __restrict__ oh, int n4) {
    int i = blockIdx.x * 256 + threadIdx.x;
    if (i >= n4) return;
    float4 v = ((const float4*)in)[i];
    ((__half2*)oh)[i * 2 + 0] = __halves2half2(__float2half(v.x), __float2half(v.y));
    ((__half2*)oh)[i * 2 + 1] = __halves2half2(__float2half(v.z), __float2half(v.w));
}

// ---------------------------------------------------------------------------
// HMMA GEMM: D[128m x 128n] = sum_k A[m,k]*B[n,k]   (fp16 in, fp32 acc)
//   128 threads (4 warps, 2x2 grid, warp tile 64x64), K-chunk 64,
//   3-stage cp.async pipeline, 2 CTAs/SM for stall interleaving.
//   mode 0: out = r[n]*D                -> HsT fp16 (m=f, n=j)
//   mode 1: out = relu(r[m]*D+bias[n])  -> Xb fp16  (m=i, n=f)
//   mode 2: out = r[m]*D+bias[n]        -> fp32     (m=i, n=f)
// ---------------------------------------------------------------------------
__global__ void __launch_bounds__(NTHREADS, 2)
gcn_gemm(const __half* __restrict__ Aop, const __half* __restrict__ Bop,
         const float* __restrict__ r, const float* __restrict__ bias,
         int lda, size_t aBatch, int ldb, size_t bBatch, int nk, int mode,
         float* __restrict__ outF, __half* __restrict__ oH) {
    extern __shared__ char smem[];
    const uint32_t smb = smem_u32(smem);
    const int tid = threadIdx.x, lane = tid & 31, wid = tid >> 5;
    const int b = blockIdx.z;
    const int m0 = blockIdx.y * 128;
    const int n0 = blockIdx.x * 128;
    const int wr = wid & 1, wc = wid >> 1;      // 2x2 warp grid
    const int m0w = wr * 64, n0w = wc * 64;

    const __half* aP = Aop + b * aBatch + (size_t)m0 * lda;
    const __half* bP = Bop + b * bBatch + (size_t)n0 * ldb;

    auto load_stage = [&](int kc, int buf) {
        const uint32_t sb = smb + buf * STAGE;
#pragma unroll
        for (int i = 0; i < 8; i++) {           // A: 1024 chunk16s
            const int chunk = i * NTHREADS + tid;
            const int row = chunk >> 3, c16 = chunk & 7;
            const uint32_t so = sw128((uint32_t)row * 128 + c16 * 16);
            cp16(sb + T_A + so, aP + (size_t)row * lda + kc * 64 + c16 * 8);
        }
#pragma unroll
        for (int i = 0; i < 8; i++) {           // B: 1024 chunk16s
            const int chunk = i * NTHREADS + tid;
            const int row = chunk >> 3, c16 = chunk & 7;
            const uint32_t so = sw128((uint32_t)row * 128 + c16 * 16);
            cp16(sb + T_B + so, bP + (size_t)row * ldb + kc * 64 + c16 * 8);
        }
    };

    const uint32_t rowA = (uint32_t)(m0w + (lane & 15)) * 128 + (lane >> 4) * 16;
    const uint32_t rowB = (uint32_t)(n0w + ((lane >> 4) << 3) + (lane & 7)) * 128 +
                          ((lane >> 3) & 1) * 16;

    float acc[4][8][4];
#pragma unroll
    for (int a = 0; a < 4; a++)
#pragma unroll
        for (int c = 0; c < 8; c++)
#pragma unroll
            for (int d = 0; d < 4; d++) acc[a][c][d] = 0.f;

    load_stage(0, 0);
    CP_COMMIT();
    if (nk > 1) load_stage(1, 1);
    CP_COMMIT();

    int buf = 0;
    for (int s = 0; s < nk; s++) {
        CP_WAIT1();
        __syncthreads();
        if (s + 2 < nk) load_stage(s + 2, (buf + 2) % NSTAGE);
        CP_COMMIT();

        const uint32_t sb = smb + buf * STAGE;
#pragma unroll
        for (int kt = 0; kt < 4; kt++) {
            uint32_t Af[4][4], Bf[4][4];
#pragma unroll
            for (int mi = 0; mi < 4; mi++)
                ldsm4(Af[mi], sb + T_A + sw128(rowA + mi * 2048 + kt * 32));
#pragma unroll
            for (int n2 = 0; n2 < 4; n2++)
                ldsm4(Bf[n2], sb + T_B + sw128(rowB + n2 * 2048 + kt * 32));
#pragma unroll
            for (int mi = 0; mi < 4; mi++)
#pragma unroll
                for (int ni = 0; ni < 8; ni++)
                    mma_f16(acc[mi][ni], Af[mi], &Bf[ni >> 1][(ni & 1) * 2]);
        }
        buf = (buf + 1) % NSTAGE;
    }

    // ---------------- epilogue --------------------------------------------
    const int g = lane >> 2, cp2 = (lane & 3) * 2;
    const float* rr = r + b * NN;

    if (mode == 0) {
#pragma unroll
        for (int mi = 0; mi < 4; mi++)
#pragma unroll
            for (int h = 0; h < 2; h++) {
                const int f = m0 + m0w + mi * 16 + g + h * 8;
                const size_t rowb = ((size_t)b * FF + f) * NN;
#pragma unroll
                for (int ni = 0; ni < 8; ni++) {
                    const int j = n0 + n0w + ni * 8 + cp2;
                    float v0 = acc[mi][ni][h * 2 + 0] * rr[j];
                    float v1 = acc[mi][ni][h * 2 + 1] * rr[j + 1];
                    *(__half2*)(oH + rowb + j) =
                        __halves2half2(__float2half(v0), __float2half(v1));
                }
            }
    } else if (mode == 1) {
#pragma unroll
        for (int mi = 0; mi < 4; mi++)
#pragma unroll
            for (int h = 0; h < 2; h++) {
                const int i = m0 + m0w + mi * 16 + g + h * 8;
                const float sc = rr[i];
                const size_t rowb = ((size_t)b * NN + i) * FF;
#pragma unroll
                for (int ni = 0; ni < 8; ni++) {
                    const int f = n0 + n0w + ni * 8 + cp2;
                    float v0 = fmaxf(sc * acc[mi][ni][h * 2 + 0] + bias[f], 0.f);
                    float v1 = fmaxf(sc * acc[mi][ni][h * 2 + 1] + bias[f + 1], 0.f);
                    *(__half2*)(oH + rowb + f) =
                        __halves2half2(__float2half(v0), __float2half(v1));
                }
            }
    } else {
#pragma unroll
        for (int mi = 0; mi < 4; mi++)
#pragma unroll
            for (int h = 0; h < 2; h++) {
                const int i = m0 + m0w + mi * 16 + g + h * 8;
                const float sc = rr[i];
                const size_t rowb = ((size_t)b * NN + i) * FF;
#pragma unroll
                for (int ni = 0; ni < 8; ni++) {
                    const int f = n0 + n0w + ni * 8 + cp2;
                    float2 v;
                    v.x = sc * acc[mi][ni][h * 2 + 0] + bias[f];
                    v.y = sc * acc[mi][ni][h * 2 + 1] + bias[f + 1];
                    *(float2*)(outF + rowb + f) = v;
                }
            }
    }
}

// ---------------------------------------------------------------------------
extern "C" void kernel_launch(void* const* d_in, const int* in_sizes, int n_in,
                              void* d_out, int out_size) {
    const float* X0  = (const float*)d_in[0];
    const float* adj = (const float*)d_in[1];
    const float* W1  = (const float*)d_in[2];
    const float* b1  = (const float*)d_in[3];
    const float* W2  = (const float*)d_in[4];
    const float* b2  = (const float*)d_in[5];
    const float* W3  = (const float*)d_in[6];
    const float* b3  = (const float*)d_in[7];
    float* out = (float*)d_out;

    float* r;
    __half *atp, *hst, *xb, *wt;
    cudaGetSymbolAddress((void**)&r,   g_r);
    cudaGetSymbolAddress((void**)&atp, g_adjT);
    cudaGetSymbolAddress((void**)&hst, g_hst);
    cudaGetSymbolAddress((void**)&xb,  g_xb);
    cudaGetSymbolAddress((void**)&wt,  g_wt);

    cudaFuncSetAttribute(gcn_gemm, cudaFuncAttributeMaxDynamicSharedMemorySize,
                         SMEM_TOTAL);

    // prep
    colsum_kernel<<<BB * NN / 64, dim3(64, 4)>>>(adj, r);                 // 0
    transpose_half<<<dim3(32, 32, BB), dim3(32, 8)>>>(adj, atp, NN, NN);  // 1
    transpose_w3<<<dim3(16, 16, 3), dim3(32, 8)>>>(W1, W2, W3, wt);       // 2
    convert_half<<<BB * NN * FF / 4 / 256, 256>>>(X0, xb, BB * NN * FF / 4); // 3

    const dim3 g1(NN / 128, FF / 128, BB);   // GEMM1: HsT[f,j]  (8,4,16)
    const dim3 g2(FF / 128, NN / 128, BB);   // GEMM2: Y[i,f]    (4,8,16)
    const float* biases[3] = {b1, b2, b3};

    for (int l = 0; l < 3; l++) {
        // GEMM1: A = W^T [f][k] (lda=FF), B = Xb [j][k] (ldb=FF)
        gcn_gemm<<<g1, NTHREADS, SMEM_TOTAL>>>(
            wt + l * FF * FF, xb, r, (const float*)0,
            FF, (size_t)0, FF, (size_t)NN * FF, FF / 64, 0,
            (float*)0, hst);
        // GEMM2: A = adjT [i][j] (lda=NN), B = HsT [f][j] (ldb=NN)
        const int mode = (l == 2) ? 2 : 1;
        gcn_gemm<<<g2, NTHREADS, SMEM_TOTAL>>>(
            atp, hst, r, biases[l],
            NN, (size_t)NN * NN, NN, (size_t)FF * NN, NN / 64, mode,
            out, xb);
    }
}

// round 14
// speedup vs baseline: 1.6513x; 1.0610x over previous
#include <cuda_runtime.h>
#include <cuda_fp16.h>
#include <stdint.h>
#include <math.h>

#define BB 16
#define NN 1024
#define FF 512

// ---------------- scratch (__device__ globals; no allocs allowed) ----------
__device__ float g_r[BB * NN];
__device__ __half g_adjT[BB * NN * NN];        // [b][i][j] = adj[b][j][i], fp16
__device__ __half g_hst[BB * FF * NN];         // HsT [b][f][j], fp16
__device__ __half g_xb[BB * NN * FF];          // activations [b][node][f], fp16
__device__ __half g_wt[3 * FF * FF];           // W^T per layer [f][k], fp16

// ---------------- base-ISA PTX helpers -------------------------------------
__device__ __forceinline__ uint32_t smem_u32(const void* p) {
    uint32_t a;
    asm("{ .reg .u64 t; cvta.to.shared.u64 t, %1; cvt.u32.u64 %0, t; }"
        : "=r"(a) : "l"(p));
    return a;
}
__device__ __forceinline__ void cp16(uint32_t s, const void* g) {
    asm volatile("cp.async.cg.shared.global [%0], [%1], 16;" :: "r"(s), "l"(g));
}
#define CP_COMMIT() asm volatile("cp.async.commit_group;" ::: "memory")
#define CP_WAIT1() asm volatile("cp.async.wait_group 1;" ::: "memory")

__device__ __forceinline__ void ldsm4(uint32_t* r, uint32_t addr) {
    asm volatile("ldmatrix.sync.aligned.m8n8.x4.shared.b16 {%0,%1,%2,%3}, [%4];"
        : "=r"(r[0]), "=r"(r[1]), "=r"(r[2]), "=r"(r[3]) : "r"(addr));
}
__device__ __forceinline__ void mma_f16(float* c, const uint32_t* a,
                                        const uint32_t* b) {
    asm volatile(
        "mma.sync.aligned.m16n8k16.row.col.f32.f16.f16.f32 "
        "{%0,%1,%2,%3}, {%4,%5,%6,%7}, {%8,%9}, {%0,%1,%2,%3};"
        : "+f"(c[0]), "+f"(c[1]), "+f"(c[2]), "+f"(c[3])
        : "r"(a[0]), "r"(a[1]), "r"(a[2]), "r"(a[3]), "r"(b[0]), "r"(b[1]));
}
__device__ __forceinline__ uint32_t sw128(uint32_t x) { return x ^ ((x >> 3) & 0x70); }

// SMEM: A (16KB, 128 rows) + B (16KB, 128 rows) per stage; 3 stages = 96KB/CTA
#define T_A  0
#define T_B  16384
#define STAGE 32768
#define NSTAGE 3
#define SMEM_TOTAL (NSTAGE * STAGE)
#define NTHREADS 128

// ---------------------------------------------------------------------------
// transpose to single fp16: out[z][C][R] = fp16(in[z][R][C])
__global__ void transpose_half(const float* __restrict__ in,
                               __half* __restrict__ oh, int R, int C) {
    __shared__ float t[32][33];
    const int i0 = blockIdx.x * 32, j0 = blockIdx.y * 32;
    const size_t zb = (size_t)blockIdx.z * R * C;
    const int tx = threadIdx.x, ty = threadIdx.y;
#pragma unroll
    for (int q = 0; q < 4; q++) {
        int j = j0 + ty + q * 8;
        t[ty + q * 8][tx] = in[zb + (size_t)j * C + i0 + tx];
    }
    __syncthreads();
#pragma unroll
    for (int q = 0; q < 4; q++) {
        int i = i0 + ty + q * 8;
        oh[zb + (size_t)i * R + j0 + tx] = __float2half(t[tx][ty + q * 8]);
    }
}

// r from adjT row sums: colsum[b,i] = sum_j adjT[b][i][j]  (contiguous fp16)
// one warp per row; fp32 accumulation; deterministic (no atomics)
__global__ void rowsum_r(const __half* __restrict__ adjT, float* __restrict__ r) {
    const int row = blockIdx.x * 8 + (threadIdx.x >> 5);   // 0 .. BB*NN-1
    const int lane = threadIdx.x & 31;
    const uint4* p = (const uint4*)(adjT + (size_t)row * NN);
    float s = 0.f;
#pragma unroll
    for (int k = 0; k < 4; k++) {
        uint4 v = p[lane + k * 32];
        const __half2* h = (const __half2*)&v;
#pragma unroll
        for (int e = 0; e < 4; e++) {
            float2 f = __half22float2(h[e]);
            s += f.x + f.y;
        }
    }
#pragma unroll
    for (int off = 16; off > 0; off >>= 1)
        s += __shfl_xor_sync(0xFFFFFFFFu, s, off);
    if (lane == 0) r[row] = (s > 0.f) ? rsqrtf(s) : 0.f;
}

// transpose all three W matrices in one launch (z selects layer)
__global__ void transpose_w3(const float* __restrict__ W1,
                             const float* __restrict__ W2,
                             const float* __restrict__ W3,
                             __half* __restrict__ oh) {
    __shared__ float t[32][33];
    const int i0 = blockIdx.x * 32, j0 = blockIdx.y * 32;
    const int z = blockIdx.z;
    const float* in = (z == 0) ? W1 : (z == 1) ? W2 : W3;
    __half* outp = oh + (size_t)z * FF * FF;
    const int tx = threadIdx.x, ty = threadIdx.y;
#pragma unroll
    for (int q = 0; q < 4; q++) {
        int j = j0 + ty + q * 8;
        t[ty + q * 8][tx] = in[(size_t)j * FF + i0 + tx];
    }
    __syncthreads();
#pragma unroll
    for (int q = 0; q < 4; q++) {
        int i = i0 + ty + q * 8;
        outp[(size_t)i * FF + j0 + tx] = __float2half(t[tx][ty + q * 8]);
    }
}

// elementwise fp32 -> fp16 convert (float4 vectorized)
__global__ void convert_half(const float* __restrict__ in,
                             __half* __restrict__ oh, int n4) {
    int i = blockIdx.x * 256 + threadIdx.x;
    if (i >= n4) return;
    float4 v = ((const float4*)in)[i];
    ((__half2*)oh)[i * 2 + 0] = __halves2half2(__float2half(v.x), __float2half(v.y));
    ((__half2*)oh)[i * 2 + 1] = __halves2half2(__float2half(v.z), __float2half(v.w));
}

// ---------------------------------------------------------------------------
// HMMA GEMM: D[128m x 128n] = sum_k A[m,k]*B[n,k]   (fp16 in, fp32 acc)
//   128 threads (4 warps, 2x2 grid, warp tile 64x64), K-chunk 64,
//   3-stage cp.async pipeline, 2 CTAs/SM for stall interleaving.
//   mode 0: out = r[n]*D                -> HsT fp16 (m=f, n=j)
//   mode 1: out = relu(r[m]*D+bias[n])  -> Xb fp16  (m=i, n=f)
//   mode 2: out = r[m]*D+bias[n]        -> fp32     (m=i, n=f)
// ---------------------------------------------------------------------------
__global__ void __launch_bounds__(NTHREADS, 2)
gcn_gemm(const __half* __restrict__ Aop, const __half* __restrict__ Bop,
         const float* __restrict__ r, const float* __restrict__ bias,
         int lda, size_t aBatch, int ldb, size_t bBatch, int nk, int mode,
         float* __restrict__ outF, __half* __restrict__ oH) {
    extern __shared__ char smem[];
    const uint32_t smb = smem_u32(smem);
    const int tid = threadIdx.x, lane = tid & 31, wid = tid >> 5;
    const int b = blockIdx.z;
    const int m0 = blockIdx.y * 128;
    const int n0 = blockIdx.x * 128;
    const int wr = wid & 1, wc = wid >> 1;      // 2x2 warp grid
    const int m0w = wr * 64, n0w = wc * 64;

    const __half* aP = Aop + b * aBatch + (size_t)m0 * lda;
    const __half* bP = Bop + b * bBatch + (size_t)n0 * ldb;

    auto load_stage = [&](int kc, int buf) {
        const uint32_t sb = smb + buf * STAGE;
#pragma unroll
        for (int i = 0; i < 8; i++) {           // A: 1024 chunk16s
            const int chunk = i * NTHREADS + tid;
            const int row = chunk >> 3, c16 = chunk & 7;
            const uint32_t so = sw128((uint32_t)row * 128 + c16 * 16);
            cp16(sb + T_A + so, aP + (size_t)row * lda + kc * 64 + c16 * 8);
        }
#pragma unroll
        for (int i = 0; i < 8; i++) {           // B: 1024 chunk16s
            const int chunk = i * NTHREADS + tid;
            const int row = chunk >> 3, c16 = chunk & 7;
            const uint32_t so = sw128((uint32_t)row * 128 + c16 * 16);
            cp16(sb + T_B + so, bP + (size_t)row * ldb + kc * 64 + c16 * 8);
        }
    };

    const uint32_t rowA = (uint32_t)(m0w + (lane & 15)) * 128 + (lane >> 4) * 16;
    const uint32_t rowB = (uint32_t)(n0w + ((lane >> 4) << 3) + (lane & 7)) * 128 +
                          ((lane >> 3) & 1) * 16;

    float acc[4][8][4];
#pragma unroll
    for (int a = 0; a < 4; a++)
#pragma unroll
        for (int c = 0; c < 8; c++)
#pragma unroll
            for (int d = 0; d < 4; d++) acc[a][c][d] = 0.f;

    load_stage(0, 0);
    CP_COMMIT();
    if (nk > 1) load_stage(1, 1);
    CP_COMMIT();

    int buf = 0;
    for (int s = 0; s < nk; s++) {
        CP_WAIT1();
        __syncthreads();
        if (s + 2 < nk) load_stage(s + 2, (buf + 2) % NSTAGE);
        CP_COMMIT();

        const uint32_t sb = smb + buf * STAGE;
#pragma unroll
        for (int kt = 0; kt < 4; kt++) {
            uint32_t Af[4][4], Bf[4][4];
#pragma unroll
            for (int mi = 0; mi < 4; mi++)
                ldsm4(Af[mi], sb + T_A + sw128(rowA + mi * 2048 + kt * 32));
#pragma unroll
            for (int n2 = 0; n2 < 4; n2++)
                ldsm4(Bf[n2], sb + T_B + sw128(rowB + n2 * 2048 + kt * 32));
#pragma unroll
            for (int mi = 0; mi < 4; mi++)
#pragma unroll
                for (int ni = 0; ni < 8; ni++)
                    mma_f16(acc[mi][ni], Af[mi], &Bf[ni >> 1][(ni & 1) * 2]);
        }
        buf = (buf + 1) % NSTAGE;
    }

    // ---------------- epilogue --------------------------------------------
    const int g = lane >> 2, cp2 = (lane & 3) * 2;
    const float* rr = r + b * NN;

    if (mode == 0) {
#pragma unroll
        for (int mi = 0; mi < 4; mi++)
#pragma unroll
            for (int h = 0; h < 2; h++) {
                const int f = m0 + m0w + mi * 16 + g + h * 8;
                const size_t rowb = ((size_t)b * FF + f) * NN;
#pragma unroll
                for (int ni = 0; ni < 8; ni++) {
                    const int j = n0 + n0w + ni * 8 + cp2;
                    float v0 = acc[mi][ni][h * 2 + 0] * rr[j];
                    float v1 = acc[mi][ni][h * 2 + 1] * rr[j + 1];
                    *(__half2*)(oH + rowb + j) =
                        __halves2half2(__float2half(v0), __float2half(v1));
                }
            }
    } else if (mode == 1) {
#pragma unroll
        for (int mi = 0; mi < 4; mi++)
#pragma unroll
            for (int h = 0; h < 2; h++) {
                const int i = m0 + m0w + mi * 16 + g + h * 8;
                const float sc = rr[i];
                const size_t rowb = ((size_t)b * NN + i) * FF;
#pragma unroll
                for (int ni = 0; ni < 8; ni++) {
                    const int f = n0 + n0w + ni * 8 + cp2;
                    float v0 = fmaxf(sc * acc[mi][ni][h * 2 + 0] + bias[f], 0.f);
                    float v1 = fmaxf(sc * acc[mi][ni][h * 2 + 1] + bias[f + 1], 0.f);
                    *(__half2*)(oH + rowb + f) =
                        __halves2half2(__float2half(v0), __float2half(v1));
                }
            }
    } else {
#pragma unroll
        for (int mi = 0; mi < 4; mi++)
#pragma unroll
            for (int h = 0; h < 2; h++) {
                const int i = m0 + m0w + mi * 16 + g + h * 8;
                const float sc = rr[i];
                const size_t rowb = ((size_t)b * NN + i) * FF;
#pragma unroll
                for (int ni = 0; ni < 8; ni++) {
                    const int f = n0 + n0w + ni * 8 + cp2;
                    float2 v;
                    v.x = sc * acc[mi][ni][h * 2 + 0] + bias[f];
                    v.y = sc * acc[mi][ni][h * 2 + 1] + bias[f + 1];
                    *(float2*)(outF + rowb + f) = v;
                }
            }
    }
}

// ---------------------------------------------------------------------------
extern "C" void kernel_launch(void* const* d_in, const int* in_sizes, int n_in,
                              void* d_out, int out_size) {
    const float* X0  = (const float*)d_in[0];
    const float* adj = (const float*)d_in[1];
    const float* W1  = (const float*)d_in[2];
    const float* b1  = (const float*)d_in[3];
    const float* W2  = (const float*)d_in[4];
    const float* b2  = (const float*)d_in[5];
    const float* W3  = (const float*)d_in[6];
    const float* b3  = (const float*)d_in[7];
    float* out = (float*)d_out;

    float* r;
    __half *atp, *hst, *xb, *wt;
    cudaGetSymbolAddress((void**)&r,   g_r);
    cudaGetSymbolAddress((void**)&atp, g_adjT);
    cudaGetSymbolAddress((void**)&hst, g_hst);
    cudaGetSymbolAddress((void**)&xb,  g_xb);
    cudaGetSymbolAddress((void**)&wt,  g_wt);

    cudaFuncSetAttribute(gcn_gemm, cudaFuncAttributeMaxDynamicSharedMemorySize,
                         SMEM_TOTAL);

    // prep (colsum now derived from fp16 adjT row sums — one less 64MB pass)
    transpose_half<<<dim3(32, 32, BB), dim3(32, 8)>>>(adj, atp, NN, NN);  // 0
    rowsum_r<<<BB * NN / 8, 256>>>(atp, r);                               // 1
    transpose_w3<<<dim3(16, 16, 3), dim3(32, 8)>>>(W1, W2, W3, wt);       // 2
    convert_half<<<BB * NN * FF / 4 / 256, 256>>>(X0, xb, BB * NN * FF / 4); // 3

    const dim3 g1(NN / 128, FF / 128, BB);   // GEMM1: HsT[f,j]  (8,4,16)
    const dim3 g2(FF / 128, NN / 128, BB);   // GEMM2: Y[i,f]    (4,8,16)
    const float* biases[3] = {b1, b2, b3};

    for (int l = 0; l < 3; l++) {
        // GEMM1: A = W^T [f][k] (lda=FF), B = Xb [j][k] (ldb=FF)
        gcn_gemm<<<g1, NTHREADS, SMEM_TOTAL>>>(
            wt + l * FF * FF, xb, r, (const float*)0,
            FF, (size_t)0, FF, (size_t)NN * FF, FF / 64, 0,
            (float*)0, hst);
        // GEMM2: A = adjT [i][j] (lda=NN), B = HsT [f][j] (ldb=NN)
        const int mode = (l == 2) ? 2 : 1;
        gcn_gemm<<<g2, NTHREADS, SMEM_TOTAL>>>(
            atp, hst, r, biases[l],
            NN, (size_t)NN * NN, NN, (size_t)FF * NN, NN / 64, mode,
            out, xb);
    }
}